// round 2
// baseline (speedup 1.0000x reference)
#include <cuda_runtime.h>
#include <cstdint>

// Problem constants
#define BB   4096
#define TT   2048
#define HH   128
#define BR   32            // batch rows per CTA
#define NCTA (BB / BR)     // 128 CTAs
#define NTHR 256           // 8 warps -> 2 per SMSP (latency hiding)
#define NOUT 8
#define HSTR 34            // smem row stride (floats): 8B-aligned pairs, conflict-free

typedef unsigned long long ull;

// ---------- packed fp32x2 helpers (Blackwell FFMA2 only reachable via PTX) ----------
__device__ __forceinline__ ull pack2(float a, float b) {
    ull r; asm("mov.b64 %0,{%1,%2};" : "=l"(r) : "f"(a), "f"(b)); return r;
}
__device__ __forceinline__ void unpack2(ull p, float& a, float& b) {
    asm("mov.b64 {%0,%1},%2;" : "=f"(a), "=f"(b) : "l"(p));
}
__device__ __forceinline__ ull fma2(ull a, ull b, ull c) {
    ull d; asm("fma.rn.f32x2 %0,%1,%2,%3;" : "=l"(d) : "l"(a), "l"(b), "l"(c)); return d;
}

// accurate activations (abs err ~1e-6, safe over 2048 steps)
__device__ __forceinline__ float sigf(float x) {
    return __fdividef(1.0f, 1.0f + __expf(-x));
}
__device__ __forceinline__ float tanhfast(float x) {
    return fmaf(2.0f, sigf(2.0f * x), -1.0f);
}

// One 16x512x128 fp32 GEMM-accumulate slice (8 row-pairs of this thread's half):
//   acc[g][rp] (+)= W[g*128 + j][k] * h[k][base + 2rp..2rp+1]  over k = 0..127
// Weights streamed from L1/L2 via LDG.128, one k4-chunk prefetch ahead.
// h read as broadcast LDS.64 pairs from [unit][row] smem layout.
#define DO_KK(C, KOFF) do {                                              \
    ull wp0 = pack2(wv0.C, wv0.C);                                       \
    ull wp1 = pack2(wv1.C, wv1.C);                                       \
    ull wp2 = pack2(wv2.C, wv2.C);                                       \
    ull wp3 = pack2(wv3.C, wv3.C);                                       \
    const float* hkk = hk + (KOFF) * HSTR;                               \
    _Pragma("unroll")                                                    \
    for (int rp = 0; rp < 8; ++rp) {                                     \
        ull hp = *(const ull*)(hkk + 2 * rp);                            \
        acc[0][rp] = fma2(wp0, hp, acc[0][rp]);                          \
        acc[1][rp] = fma2(wp1, hp, acc[1][rp]);                          \
        acc[2][rp] = fma2(wp2, hp, acc[2][rp]);                          \
        acc[3][rp] = fma2(wp3, hp, acc[3][rp]);                          \
    }                                                                    \
} while (0)

__device__ __forceinline__ void gemm_acc(ull (&acc)[4][8],
                                         const float4* __restrict__ wb,
                                         const float* __restrict__ hbuf)
{
    float4 wv0 = __ldg(wb + 0);
    float4 wv1 = __ldg(wb + 4096);
    float4 wv2 = __ldg(wb + 8192);
    float4 wv3 = __ldg(wb + 12288);
    #pragma unroll 1
    for (int k4 = 0; k4 < 32; ++k4) {
        const int kn = (k4 < 31) ? (k4 + 1) : 31;     // prefetch next chunk
        float4 wn0 = __ldg(wb + kn);
        float4 wn1 = __ldg(wb + 4096 + kn);
        float4 wn2 = __ldg(wb + 8192 + kn);
        float4 wn3 = __ldg(wb + 12288 + kn);
        const float* hk = hbuf + k4 * (4 * HSTR);
        DO_KK(x, 0); DO_KK(y, 1); DO_KK(z, 2); DO_KK(w, 3);
        wv0 = wn0; wv1 = wn1; wv2 = wn2; wv3 = wn3;
    }
}

// Dynamic smem layout (floats)
#define SM_H1 0                          // [2][128][HSTR]
#define SM_H2 (SM_H1 + 2 * HH * HSTR)    // [2][128][HSTR]
#define SM_C1 (SM_H2 + 2 * HH * HSTR)    // [32][128]
#define SM_C2 (SM_C1 + BR * HH)          // [32][128]
#define SM_XS (SM_C2 + BR * HH)          // [64][HSTR]  x-tile, transposed
#define SM_W1 (SM_XS + 64 * HSTR)        // [128][8]  (transposed: [k][oo])
#define SM_W2 (SM_W1 + NOUT * HH)        // [128][8]  (transposed)
#define SM_B1 (SM_W2 + NOUT * HH)        // [8]
#define SM_B2 (SM_B1 + NOUT)             // [8]
#define SM_TOT (SM_B2 + NOUT)

__global__ void __launch_bounds__(NTHR, 1)
lstm_kernel(const float* __restrict__ x,
            const float* __restrict__ wih1, const float* __restrict__ whh1,
            const float* __restrict__ bih1, const float* __restrict__ bhh1,
            const float* __restrict__ wih2, const float* __restrict__ whh2,
            const float* __restrict__ bih2, const float* __restrict__ bhh2,
            const float* __restrict__ W1, const float* __restrict__ b1,
            const float* __restrict__ W2, const float* __restrict__ b2,
            float* __restrict__ out)
{
    extern __shared__ float sm[];
    float* h1s = sm + SM_H1;
    float* h2s = sm + SM_H2;
    float* c1s = sm + SM_C1;
    float* c2s = sm + SM_C2;
    float* xs  = sm + SM_XS;
    float* W1s = sm + SM_W1;
    float* W2s = sm + SM_W2;
    float* b1s = sm + SM_B1;
    float* b2s = sm + SM_B2;

    const int tid = threadIdx.x;
    const int j   = tid & 127;           // hidden unit owned by this thread
    const int rh  = tid >> 7;            // row half: rows [rh*16, rh*16+16)
    const int r0  = blockIdx.x * BR;     // first batch row of this CTA

    // ---- init smem: zero states, stage output weights (transposed [k][oo]) ----
    for (int i = tid; i < 2 * HH * HSTR; i += NTHR) { h1s[i] = 0.0f; h2s[i] = 0.0f; }
    for (int i = tid; i < BR * HH;       i += NTHR) { c1s[i] = 0.0f; c2s[i] = 0.0f; }
    for (int i = tid; i < NOUT * HH;     i += NTHR) {
        const int oo = i / HH, k = i % HH;
        W1s[k * NOUT + oo] = W1[i];
        W2s[k * NOUT + oo] = W2[i];
    }
    if (tid < NOUT) { b1s[tid] = b1[tid]; b2s[tid] = b2[tid]; }

    // ---- per-thread constants: fused biases + input weight, packed ----
    ull b1p[4], b2p[4], wi1p[4];
    #pragma unroll
    for (int g = 0; g < 4; ++g) {
        const int row = g * HH + j;
        const float bb1 = bih1[row] + bhh1[row];
        const float bb2 = bih2[row] + bhh2[row];
        b1p[g]  = pack2(bb1, bb1);
        b2p[g]  = pack2(bb2, bb2);
        const float wv = wih1[row];   // W_ih1 is (512,1)
        wi1p[g] = pack2(wv, wv);
    }

    // weight bases: gate g row at + g*4096 float4
    const float4* whh1b = (const float4*)whh1 + j * 32;
    const float4* wih2b = (const float4*)wih2 + j * 32;
    const float4* whh2b = (const float4*)whh2 + j * 32;

    __syncthreads();

    ull acc[4][8];
    const int rbase   = rh * 16;               // first row of this thread's half
    const int rr_out  = tid >> 3;              // projection: one (row, out) per thread
    const int oo_out  = tid & 7;
    const size_t OUTS_BASE = (size_t)BB * NOUT;   // outputs follow output_cyto

    #pragma unroll 1
    for (int t = 0; t < TT; ++t) {
        const int cur = t & 1, nxt = cur ^ 1;
        float* h1c = h1s + cur * (HH * HSTR);
        float* h1n = h1s + nxt * (HH * HSTR);
        float* h2c = h2s + cur * (HH * HSTR);
        float* h2n = h2s + nxt * (HH * HSTR);

        // ---- stage 64 steps of x, transposed to [t][row] for paired loads ----
        if ((t & 63) == 0) {
            __syncthreads();
            for (int idx = tid; idx < BR * 64; idx += NTHR) {
                const int rr = idx >> 6, tt2 = idx & 63;
                xs[tt2 * HSTR + rr] = x[(size_t)(r0 + rr) * TT + t + tt2];
            }
            __syncthreads();
        }
        const float* xrow = xs + (t & 63) * HSTR + rbase;

        // ---------------- cell 1 ----------------
        #pragma unroll
        for (int rp = 0; rp < 8; ++rp) {
            const ull xp = *(const ull*)(xrow + 2 * rp);
            acc[0][rp] = fma2(wi1p[0], xp, b1p[0]);
            acc[1][rp] = fma2(wi1p[1], xp, b1p[1]);
            acc[2][rp] = fma2(wi1p[2], xp, b1p[2]);
            acc[3][rp] = fma2(wi1p[3], xp, b1p[3]);
        }
        gemm_acc(acc, whh1b, h1c + rbase);

        #pragma unroll
        for (int rp = 0; rp < 8; ++rp) {
            float iv0, iv1, fv0, fv1, gv0, gv1, ov0, ov1;
            unpack2(acc[0][rp], iv0, iv1);
            unpack2(acc[1][rp], fv0, fv1);
            unpack2(acc[2][rp], gv0, gv1);
            unpack2(acc[3][rp], ov0, ov1);
            {
                const int r = rbase + 2 * rp;
                const float c  = c1s[r * HH + j];
                const float cn = sigf(fv0) * c + sigf(iv0) * tanhfast(gv0);
                c1s[r * HH + j] = cn;
                h1n[j * HSTR + r] = sigf(ov0) * tanhfast(cn);
            }
            {
                const int r = rbase + 2 * rp + 1;
                const float c  = c1s[r * HH + j];
                const float cn = sigf(fv1) * c + sigf(iv1) * tanhfast(gv1);
                c1s[r * HH + j] = cn;
                h1n[j * HSTR + r] = sigf(ov1) * tanhfast(cn);
            }
        }
        __syncthreads();

        // ---------------- cell 2 ----------------
        #pragma unroll
        for (int rp = 0; rp < 8; ++rp) {
            acc[0][rp] = b2p[0]; acc[1][rp] = b2p[1];
            acc[2][rp] = b2p[2]; acc[3][rp] = b2p[3];
        }
        gemm_acc(acc, wih2b, h1n + rbase);
        gemm_acc(acc, whh2b, h2c + rbase);

        #pragma unroll
        for (int rp = 0; rp < 8; ++rp) {
            float iv0, iv1, fv0, fv1, gv0, gv1, ov0, ov1;
            unpack2(acc[0][rp], iv0, iv1);
            unpack2(acc[1][rp], fv0, fv1);
            unpack2(acc[2][rp], gv0, gv1);
            unpack2(acc[3][rp], ov0, ov1);
            {
                const int r = rbase + 2 * rp;
                const float c  = c2s[r * HH + j];
                const float cn = sigf(fv0) * c + sigf(iv0) * tanhfast(gv0);
                c2s[r * HH + j] = cn;
                h2n[j * HSTR + r] = sigf(ov0) * tanhfast(cn);
            }
            {
                const int r = rbase + 2 * rp + 1;
                const float c  = c2s[r * HH + j];
                const float cn = sigf(fv1) * c + sigf(iv1) * tanhfast(gv1);
                c2s[r * HH + j] = cn;
                h2n[j * HSTR + r] = sigf(ov1) * tanhfast(cn);
            }
        }
        __syncthreads();

        // ------- out projection: out_mask = h2 @ W1^T + b1 (one dot per thread) -------
        {
            float a0 = b1s[oo_out];
            const float* wr = W1s + oo_out;
            #pragma unroll 8
            for (int k = 0; k < HH; ++k) {
                a0 = fmaf(h2n[k * HSTR + rr_out], wr[k * NOUT], a0);
            }
            out[OUTS_BASE + ((size_t)(r0 + rr_out) * TT + t) * NOUT + oo_out] = a0;
        }
    }

    // ---------------- final: output_cyto = h2_final @ W2^T + b2 ----------------
    // TT even -> final h2 lives in buffer 0
    {
        const float* hf = h2s;  // buffer 0
        float a0 = b2s[oo_out];
        const float* wr = W2s + oo_out;
        #pragma unroll 8
        for (int k = 0; k < HH; ++k) {
            a0 = fmaf(hf[k * HSTR + rr_out], wr[k * NOUT], a0);
        }
        out[(size_t)(r0 + rr_out) * NOUT + oo_out] = a0;
    }
}

extern "C" void kernel_launch(void* const* d_in, const int* in_sizes, int n_in,
                              void* d_out, int out_size)
{
    (void)n_in; (void)out_size;
    // input order: x, [future], W_ih1, W_hh1, b_ih1, b_hh1, W_ih2, W_hh2,
    //              b_ih2, b_hh2, W1, b1, W2, b2.
    const int o = (n_in >= 2 && in_sizes[1] == 1) ? 2 : 1;

    const float* x    = (const float*)d_in[0];
    const float* wih1 = (const float*)d_in[o + 0];
    const float* whh1 = (const float*)d_in[o + 1];
    const float* bih1 = (const float*)d_in[o + 2];
    const float* bhh1 = (const float*)d_in[o + 3];
    const float* wih2 = (const float*)d_in[o + 4];
    const float* whh2 = (const float*)d_in[o + 5];
    const float* bih2 = (const float*)d_in[o + 6];
    const float* bhh2 = (const float*)d_in[o + 7];
    const float* W1   = (const float*)d_in[o + 8];
    const float* b1   = (const float*)d_in[o + 9];
    const float* W2   = (const float*)d_in[o + 10];
    const float* b2   = (const float*)d_in[o + 11];

    const size_t smem = (size_t)SM_TOT * sizeof(float);   // ~116.6 KB
    cudaFuncSetAttribute(lstm_kernel,
                         cudaFuncAttributeMaxDynamicSharedMemorySize, (int)smem);

    lstm_kernel<<<NCTA, NTHR, smem>>>(x, wih1, whh1, bih1, bhh1,
                                      wih2, whh2, bih2, bhh2,
                                      W1, b1, W2, b2, (float*)d_out);
}

// round 4
// speedup vs baseline: 1.7730x; 1.7730x over previous
#include <cuda_runtime.h>
#include <cstdint>

// Problem constants
#define BB   4096
#define TT   2048
#define HH   128
#define BR   32            // batch rows per CTA
#define NCTA (BB / BR)     // 128 CTAs
#define NTHR 256           // 8 warps -> 2 per SMSP
#define NOUT 8
#define HSTR 36            // smem row stride (floats): 144B, 16B-aligned (LDS.128-safe)

typedef unsigned long long ull;

// ---------- packed fp32x2 helpers ----------
__device__ __forceinline__ ull pack2(float a, float b) {
    ull r; asm("mov.b64 %0,{%1,%2};" : "=l"(r) : "f"(a), "f"(b)); return r;
}
__device__ __forceinline__ void unpack2(ull p, float& a, float& b) {
    asm("mov.b64 {%0,%1},%2;" : "=f"(a), "=f"(b) : "l"(p));
}
__device__ __forceinline__ ull fma2(ull a, ull b, ull c) {
    ull d; asm("fma.rn.f32x2 %0,%1,%2,%3;" : "=l"(d) : "l"(a), "l"(b), "l"(c)); return d;
}

__device__ __forceinline__ float sigf(float x) {
    return __fdividef(1.0f, 1.0f + __expf(-x));
}
__device__ __forceinline__ float tanhfast(float x) {
    return fmaf(2.0f, sigf(2.0f * x), -1.0f);
}

// Transposed weights: [mat][k*128 + j], float4 = (gate0,gate1,gate2,gate3) for unit j at col k.
// Coalesced: lanes j..j+31 read 512B contiguous (4 lines per LDG.128, not 32).
__device__ float4 g_wt[3][HH * HH];

__global__ void transpose_w_kernel(const float* __restrict__ whh1,
                                   const float* __restrict__ wih2,
                                   const float* __restrict__ whh2)
{
    const int idx = blockIdx.x * blockDim.x + threadIdx.x;   // 0..16383
    if (idx >= HH * HH) return;
    const int k = idx >> 7, j = idx & 127;
    const float* Ws[3] = { whh1, wih2, whh2 };
    #pragma unroll
    for (int m = 0; m < 3; ++m) {
        const float* W = Ws[m];
        g_wt[m][idx] = make_float4(W[(0 * HH + j) * HH + k],
                                   W[(1 * HH + j) * HH + k],
                                   W[(2 * HH + j) * HH + k],
                                   W[(3 * HH + j) * HH + k]);
    }
}

// 16x512x128 fp32 GEMM-accumulate slice (this thread's 8 row-pairs, unit j, 4 gates):
//   acc[g][rp] (+)= Wt[k][j].gate_g * h[k][rbase + 2rp .. 2rp+1]
// Weights: 1 coalesced LDG.128/k (all 4 gates), prefetched 4 k ahead (covers L2 lat).
// h: broadcast LDS.128 row-quads (conflict-free).
__device__ __forceinline__ void gemm_acc(ull (&acc)[4][8],
                                         const float4* __restrict__ wt,   // g_wt[m] + j
                                         const float* __restrict__ hbuf)  // h + rbase
{
    float4 wv[4];
    #pragma unroll
    for (int i = 0; i < 4; ++i) wv[i] = __ldg(wt + i * HH);
    #pragma unroll 1
    for (int k4 = 0; k4 < 32; ++k4) {
        float4 wn[4];
        const int kb = (k4 < 31) ? (k4 + 1) * 4 : 124;    // prefetch next 4 k
        #pragma unroll
        for (int i = 0; i < 4; ++i) wn[i] = __ldg(wt + (kb + i) * HH);
        const float* hk = hbuf + (k4 * 4) * HSTR;
        #pragma unroll
        for (int kk = 0; kk < 4; ++kk) {
            const ull wp0 = pack2(wv[kk].x, wv[kk].x);
            const ull wp1 = pack2(wv[kk].y, wv[kk].y);
            const ull wp2 = pack2(wv[kk].z, wv[kk].z);
            const ull wp3 = pack2(wv[kk].w, wv[kk].w);
            const float* hkk = hk + kk * HSTR;
            #pragma unroll
            for (int rq = 0; rq < 4; ++rq) {               // quad of rows: LDS.128
                const float4 h4 = *(const float4*)(hkk + 4 * rq);
                const ull hp0 = pack2(h4.x, h4.y);
                const ull hp1 = pack2(h4.z, h4.w);
                const int rp = 2 * rq;
                acc[0][rp]   = fma2(wp0, hp0, acc[0][rp]);
                acc[1][rp]   = fma2(wp1, hp0, acc[1][rp]);
                acc[2][rp]   = fma2(wp2, hp0, acc[2][rp]);
                acc[3][rp]   = fma2(wp3, hp0, acc[3][rp]);
                acc[0][rp+1] = fma2(wp0, hp1, acc[0][rp+1]);
                acc[1][rp+1] = fma2(wp1, hp1, acc[1][rp+1]);
                acc[2][rp+1] = fma2(wp2, hp1, acc[2][rp+1]);
                acc[3][rp+1] = fma2(wp3, hp1, acc[3][rp+1]);
            }
        }
        #pragma unroll
        for (int i = 0; i < 4; ++i) wv[i] = wn[i];
    }
}

// Dynamic smem layout (floats) — c lives in registers
#define SM_H1 0                          // [2][128][HSTR]
#define SM_H2 (SM_H1 + 2 * HH * HSTR)    // [2][128][HSTR]
#define SM_XS (SM_H2 + 2 * HH * HSTR)    // [64][HSTR]  x-tile, transposed
#define SM_W1 (SM_XS + 64 * HSTR)        // [128][8]  (transposed [k][oo])
#define SM_W2 (SM_W1 + NOUT * HH)        // [128][8]
#define SM_B1 (SM_W2 + NOUT * HH)        // [8]
#define SM_B2 (SM_B1 + NOUT)             // [8]
#define SM_TOT (SM_B2 + NOUT)

__global__ void __launch_bounds__(NTHR, 1)
lstm_kernel(const float* __restrict__ x,
            const float* __restrict__ wih1,
            const float* __restrict__ bih1, const float* __restrict__ bhh1,
            const float* __restrict__ bih2, const float* __restrict__ bhh2,
            const float* __restrict__ W1, const float* __restrict__ b1,
            const float* __restrict__ W2, const float* __restrict__ b2,
            float* __restrict__ out)
{
    extern __shared__ float sm[];
    float* h1s = sm + SM_H1;
    float* h2s = sm + SM_H2;
    float* xs  = sm + SM_XS;
    float* W1s = sm + SM_W1;
    float* W2s = sm + SM_W2;
    float* b1s = sm + SM_B1;
    float* b2s = sm + SM_B2;

    const int tid = threadIdx.x;
    const int j   = tid & 127;           // hidden unit owned by this thread
    const int rh  = tid >> 7;            // row half: rows [rh*16, rh*16+16)
    const int r0  = blockIdx.x * BR;     // first batch row of this CTA

    // ---- init smem ----
    for (int i = tid; i < 2 * HH * HSTR; i += NTHR) { h1s[i] = 0.0f; h2s[i] = 0.0f; }
    for (int i = tid; i < NOUT * HH;     i += NTHR) {
        const int oo = i / HH, k = i % HH;
        W1s[k * NOUT + oo] = W1[i];
        W2s[k * NOUT + oo] = W2[i];
    }
    if (tid < NOUT) { b1s[tid] = b1[tid]; b2s[tid] = b2[tid]; }

    // ---- per-thread constants ----
    ull b1p[4], b2p[4], wi1p[4];
    #pragma unroll
    for (int g = 0; g < 4; ++g) {
        const int row = g * HH + j;
        const float bb1 = bih1[row] + bhh1[row];
        const float bb2 = bih2[row] + bhh2[row];
        b1p[g]  = pack2(bb1, bb1);
        b2p[g]  = pack2(bb2, bb2);
        const float wv = wih1[row];   // W_ih1 is (512,1)
        wi1p[g] = pack2(wv, wv);
    }

    // cell state in registers: c[cell][local row 0..15] for unit j
    float c1r[16], c2r[16];
    #pragma unroll
    for (int i = 0; i < 16; ++i) { c1r[i] = 0.0f; c2r[i] = 0.0f; }

    const float4* wt1 = g_wt[0] + j;   // whh1 transposed
    const float4* wt2 = g_wt[1] + j;   // wih2 transposed
    const float4* wt3 = g_wt[2] + j;   // whh2 transposed

    __syncthreads();

    ull acc[4][8];
    const int rbase   = rh * 16;
    const int rr_out  = tid >> 3;
    const int oo_out  = tid & 7;
    const size_t OUTS_BASE = (size_t)BB * NOUT;

    #pragma unroll 1
    for (int t = 0; t < TT; ++t) {
        const int cur = t & 1, nxt = cur ^ 1;
        float* h1c = h1s + cur * (HH * HSTR);
        float* h1n = h1s + nxt * (HH * HSTR);
        float* h2c = h2s + cur * (HH * HSTR);
        float* h2n = h2s + nxt * (HH * HSTR);

        // ---- stage 64 steps of x, transposed to [t][row] ----
        if ((t & 63) == 0) {
            __syncthreads();
            for (int idx = tid; idx < BR * 64; idx += NTHR) {
                const int rr = idx >> 6, tt2 = idx & 63;
                xs[tt2 * HSTR + rr] = x[(size_t)(r0 + rr) * TT + t + tt2];
            }
            __syncthreads();
        }
        const float* xrow = xs + (t & 63) * HSTR + rbase;

        // ---------------- cell 1 ----------------
        #pragma unroll
        for (int rq = 0; rq < 4; ++rq) {
            const float4 x4 = *(const float4*)(xrow + 4 * rq);
            const ull xp0 = pack2(x4.x, x4.y);
            const ull xp1 = pack2(x4.z, x4.w);
            const int rp = 2 * rq;
            acc[0][rp]   = fma2(wi1p[0], xp0, b1p[0]);
            acc[1][rp]   = fma2(wi1p[1], xp0, b1p[1]);
            acc[2][rp]   = fma2(wi1p[2], xp0, b1p[2]);
            acc[3][rp]   = fma2(wi1p[3], xp0, b1p[3]);
            acc[0][rp+1] = fma2(wi1p[0], xp1, b1p[0]);
            acc[1][rp+1] = fma2(wi1p[1], xp1, b1p[1]);
            acc[2][rp+1] = fma2(wi1p[2], xp1, b1p[2]);
            acc[3][rp+1] = fma2(wi1p[3], xp1, b1p[3]);
        }
        gemm_acc(acc, wt1, h1c + rbase);

        #pragma unroll
        for (int rp = 0; rp < 8; ++rp) {
            float iv0, iv1, fv0, fv1, gv0, gv1, ov0, ov1;
            unpack2(acc[0][rp], iv0, iv1);
            unpack2(acc[1][rp], fv0, fv1);
            unpack2(acc[2][rp], gv0, gv1);
            unpack2(acc[3][rp], ov0, ov1);
            {
                const float cn = sigf(fv0) * c1r[2*rp] + sigf(iv0) * tanhfast(gv0);
                c1r[2*rp] = cn;
                h1n[j * HSTR + rbase + 2*rp] = sigf(ov0) * tanhfast(cn);
            }
            {
                const float cn = sigf(fv1) * c1r[2*rp+1] + sigf(iv1) * tanhfast(gv1);
                c1r[2*rp+1] = cn;
                h1n[j * HSTR + rbase + 2*rp+1] = sigf(ov1) * tanhfast(cn);
            }
        }
        __syncthreads();

        // ---------------- cell 2 ----------------
        #pragma unroll
        for (int rp = 0; rp < 8; ++rp) {
            acc[0][rp] = b2p[0]; acc[1][rp] = b2p[1];
            acc[2][rp] = b2p[2]; acc[3][rp] = b2p[3];
        }
        gemm_acc(acc, wt2, h1n + rbase);
        gemm_acc(acc, wt3, h2c + rbase);

        #pragma unroll
        for (int rp = 0; rp < 8; ++rp) {
            float iv0, iv1, fv0, fv1, gv0, gv1, ov0, ov1;
            unpack2(acc[0][rp], iv0, iv1);
            unpack2(acc[1][rp], fv0, fv1);
            unpack2(acc[2][rp], gv0, gv1);
            unpack2(acc[3][rp], ov0, ov1);
            {
                const float cn = sigf(fv0) * c2r[2*rp] + sigf(iv0) * tanhfast(gv0);
                c2r[2*rp] = cn;
                h2n[j * HSTR + rbase + 2*rp] = sigf(ov0) * tanhfast(cn);
            }
            {
                const float cn = sigf(fv1) * c2r[2*rp+1] + sigf(iv1) * tanhfast(gv1);
                c2r[2*rp+1] = cn;
                h2n[j * HSTR + rbase + 2*rp+1] = sigf(ov1) * tanhfast(cn);
            }
        }
        __syncthreads();

        // ------- out projection: out_mask = h2 @ W1^T + b1 (one dot per thread) -------
        {
            float a0 = b1s[oo_out];
            const float* wr = W1s + oo_out;
            #pragma unroll 8
            for (int k = 0; k < HH; ++k) {
                a0 = fmaf(h2n[k * HSTR + rr_out], wr[k * NOUT], a0);
            }
            out[OUTS_BASE + ((size_t)(r0 + rr_out) * TT + t) * NOUT + oo_out] = a0;
        }
    }

    // ---------------- final: output_cyto = h2_final @ W2^T + b2 ----------------
    // TT even -> final h2 lives in buffer 0
    {
        const float* hf = h2s;
        float a0 = b2s[oo_out];
        const float* wr = W2s + oo_out;
        #pragma unroll 8
        for (int k = 0; k < HH; ++k) {
            a0 = fmaf(hf[k * HSTR + rr_out], wr[k * NOUT], a0);
        }
        out[(size_t)(r0 + rr_out) * NOUT + oo_out] = a0;
    }
}

extern "C" void kernel_launch(void* const* d_in, const int* in_sizes, int n_in,
                              void* d_out, int out_size)
{
    (void)n_in; (void)out_size;
    const int o = (n_in >= 2 && in_sizes[1] == 1) ? 2 : 1;

    const float* x    = (const float*)d_in[0];
    const float* wih1 = (const float*)d_in[o + 0];
    const float* whh1 = (const float*)d_in[o + 1];
    const float* bih1 = (const float*)d_in[o + 2];
    const float* bhh1 = (const float*)d_in[o + 3];
    const float* wih2 = (const float*)d_in[o + 4];
    const float* whh2 = (const float*)d_in[o + 5];
    const float* bih2 = (const float*)d_in[o + 6];
    const float* bhh2 = (const float*)d_in[o + 7];
    const float* W1   = (const float*)d_in[o + 8];
    const float* b1   = (const float*)d_in[o + 9];
    const float* W2   = (const float*)d_in[o + 10];
    const float* b2   = (const float*)d_in[o + 11];

    // 1) transpose weights into __device__ scratch (k-major, gates packed)
    transpose_w_kernel<<<(HH * HH + 255) / 256, 256>>>(whh1, wih2, whh2);

    // 2) main persistent recurrence kernel
    const size_t smem = (size_t)SM_TOT * sizeof(float);   // ~91 KB
    cudaFuncSetAttribute(lstm_kernel,
                         cudaFuncAttributeMaxDynamicSharedMemorySize, (int)smem);
    lstm_kernel<<<NCTA, NTHR, smem>>>(x, wih1, bih1, bhh1, bih2, bhh2,
                                      W1, b1, W2, b2, (float*)d_out);
}

// round 5
// speedup vs baseline: 1.7741x; 1.0006x over previous
#include <cuda_runtime.h>
#include <cstdint>

// Problem constants
#define BB   4096
#define TT   2048
#define HH   128
#define BR   32            // batch rows per CTA
#define NCTA (BB / BR)     // 128 CTAs
#define NTHR 256           // 8 warps -> 2 per SMSP
#define NOUT 8
#define HSTR 36            // smem row stride (floats): 144B, 16B-aligned (LDS.128-safe)

typedef unsigned long long ull;

// ---------- packed fp32x2 helpers ----------
__device__ __forceinline__ ull pack2(float a, float b) {
    ull r; asm("mov.b64 %0,{%1,%2};" : "=l"(r) : "f"(a), "f"(b)); return r;
}
__device__ __forceinline__ void unpack2(ull p, float& a, float& b) {
    asm("mov.b64 {%0,%1},%2;" : "=f"(a), "=f"(b) : "l"(p));
}
__device__ __forceinline__ ull fma2(ull a, ull b, ull c) {
    ull d; asm("fma.rn.f32x2 %0,%1,%2,%3;" : "=l"(d) : "l"(a), "l"(b), "l"(c)); return d;
}

__device__ __forceinline__ float sigf(float x) {
    return __fdividef(1.0f, 1.0f + __expf(-x));
}
__device__ __forceinline__ float tanhfast(float x) {
    return fmaf(2.0f, sigf(2.0f * x), -1.0f);
}

// Transposed weights: [mat][k*128 + j], float4 = (gate0,gate1,gate2,gate3) for unit j at col k.
// Coalesced: lanes j..j+31 read 512B contiguous (4 lines per LDG.128, not 32).
__device__ float4 g_wt[3][HH * HH];

__global__ void transpose_w_kernel(const float* __restrict__ whh1,
                                   const float* __restrict__ wih2,
                                   const float* __restrict__ whh2)
{
    const int idx = blockIdx.x * blockDim.x + threadIdx.x;   // 0..16383
    if (idx >= HH * HH) return;
    const int k = idx >> 7, j = idx & 127;
    const float* Ws[3] = { whh1, wih2, whh2 };
    #pragma unroll
    for (int m = 0; m < 3; ++m) {
        const float* W = Ws[m];
        g_wt[m][idx] = make_float4(W[(0 * HH + j) * HH + k],
                                   W[(1 * HH + j) * HH + k],
                                   W[(2 * HH + j) * HH + k],
                                   W[(3 * HH + j) * HH + k]);
    }
}

// 16x512x128 fp32 GEMM-accumulate slice (this thread's 8 row-pairs, unit j, 4 gates):
//   acc[g][rp] (+)= Wt[k][j].gate_g * h[k][rbase + 2rp .. 2rp+1]
// Weights: 1 coalesced LDG.128/k (all 4 gates), prefetched 4 k ahead (covers L2 lat).
// h: broadcast LDS.128 row-quads (conflict-free).
__device__ __forceinline__ void gemm_acc(ull (&acc)[4][8],
                                         const float4* __restrict__ wt,   // g_wt[m] + j
                                         const float* __restrict__ hbuf)  // h + rbase
{
    float4 wv[4];
    #pragma unroll
    for (int i = 0; i < 4; ++i) wv[i] = __ldg(wt + i * HH);
    #pragma unroll 1
    for (int k4 = 0; k4 < 32; ++k4) {
        float4 wn[4];
        const int kb = (k4 < 31) ? (k4 + 1) * 4 : 124;    // prefetch next 4 k
        #pragma unroll
        for (int i = 0; i < 4; ++i) wn[i] = __ldg(wt + (kb + i) * HH);
        const float* hk = hbuf + (k4 * 4) * HSTR;
        #pragma unroll
        for (int kk = 0; kk < 4; ++kk) {
            const ull wp0 = pack2(wv[kk].x, wv[kk].x);
            const ull wp1 = pack2(wv[kk].y, wv[kk].y);
            const ull wp2 = pack2(wv[kk].z, wv[kk].z);
            const ull wp3 = pack2(wv[kk].w, wv[kk].w);
            const float* hkk = hk + kk * HSTR;
            #pragma unroll
            for (int rq = 0; rq < 4; ++rq) {               // quad of rows: LDS.128
                const float4 h4 = *(const float4*)(hkk + 4 * rq);
                const ull hp0 = pack2(h4.x, h4.y);
                const ull hp1 = pack2(h4.z, h4.w);
                const int rp = 2 * rq;
                acc[0][rp]   = fma2(wp0, hp0, acc[0][rp]);
                acc[1][rp]   = fma2(wp1, hp0, acc[1][rp]);
                acc[2][rp]   = fma2(wp2, hp0, acc[2][rp]);
                acc[3][rp]   = fma2(wp3, hp0, acc[3][rp]);
                acc[0][rp+1] = fma2(wp0, hp1, acc[0][rp+1]);
                acc[1][rp+1] = fma2(wp1, hp1, acc[1][rp+1]);
                acc[2][rp+1] = fma2(wp2, hp1, acc[2][rp+1]);
                acc[3][rp+1] = fma2(wp3, hp1, acc[3][rp+1]);
            }
        }
        #pragma unroll
        for (int i = 0; i < 4; ++i) wv[i] = wn[i];
    }
}

// Dynamic smem layout (floats) — c lives in registers
#define SM_H1 0                          // [2][128][HSTR]
#define SM_H2 (SM_H1 + 2 * HH * HSTR)    // [2][128][HSTR]
#define SM_XS (SM_H2 + 2 * HH * HSTR)    // [64][HSTR]  x-tile, transposed
#define SM_W1 (SM_XS + 64 * HSTR)        // [128][8]  (transposed [k][oo])
#define SM_W2 (SM_W1 + NOUT * HH)        // [128][8]
#define SM_B1 (SM_W2 + NOUT * HH)        // [8]
#define SM_B2 (SM_B1 + NOUT)             // [8]
#define SM_TOT (SM_B2 + NOUT)

__global__ void __launch_bounds__(NTHR, 1)
lstm_kernel(const float* __restrict__ x,
            const float* __restrict__ wih1,
            const float* __restrict__ bih1, const float* __restrict__ bhh1,
            const float* __restrict__ bih2, const float* __restrict__ bhh2,
            const float* __restrict__ W1, const float* __restrict__ b1,
            const float* __restrict__ W2, const float* __restrict__ b2,
            float* __restrict__ out)
{
    extern __shared__ float sm[];
    float* h1s = sm + SM_H1;
    float* h2s = sm + SM_H2;
    float* xs  = sm + SM_XS;
    float* W1s = sm + SM_W1;
    float* W2s = sm + SM_W2;
    float* b1s = sm + SM_B1;
    float* b2s = sm + SM_B2;

    const int tid = threadIdx.x;
    const int j   = tid & 127;           // hidden unit owned by this thread
    const int rh  = tid >> 7;            // row half: rows [rh*16, rh*16+16)
    const int r0  = blockIdx.x * BR;     // first batch row of this CTA

    // ---- init smem ----
    for (int i = tid; i < 2 * HH * HSTR; i += NTHR) { h1s[i] = 0.0f; h2s[i] = 0.0f; }
    for (int i = tid; i < NOUT * HH;     i += NTHR) {
        const int oo = i / HH, k = i % HH;
        W1s[k * NOUT + oo] = W1[i];
        W2s[k * NOUT + oo] = W2[i];
    }
    if (tid < NOUT) { b1s[tid] = b1[tid]; b2s[tid] = b2[tid]; }

    // ---- per-thread constants ----
    ull b1p[4], b2p[4], wi1p[4];
    #pragma unroll
    for (int g = 0; g < 4; ++g) {
        const int row = g * HH + j;
        const float bb1 = bih1[row] + bhh1[row];
        const float bb2 = bih2[row] + bhh2[row];
        b1p[g]  = pack2(bb1, bb1);
        b2p[g]  = pack2(bb2, bb2);
        const float wv = wih1[row];   // W_ih1 is (512,1)
        wi1p[g] = pack2(wv, wv);
    }

    // cell state in registers: c[cell][local row 0..15] for unit j
    float c1r[16], c2r[16];
    #pragma unroll
    for (int i = 0; i < 16; ++i) { c1r[i] = 0.0f; c2r[i] = 0.0f; }

    const float4* wt1 = g_wt[0] + j;   // whh1 transposed
    const float4* wt2 = g_wt[1] + j;   // wih2 transposed
    const float4* wt3 = g_wt[2] + j;   // whh2 transposed

    __syncthreads();

    ull acc[4][8];
    const int rbase   = rh * 16;
    const int rr_out  = tid >> 3;
    const int oo_out  = tid & 7;
    const size_t OUTS_BASE = (size_t)BB * NOUT;

    #pragma unroll 1
    for (int t = 0; t < TT; ++t) {
        const int cur = t & 1, nxt = cur ^ 1;
        float* h1c = h1s + cur * (HH * HSTR);
        float* h1n = h1s + nxt * (HH * HSTR);
        float* h2c = h2s + cur * (HH * HSTR);
        float* h2n = h2s + nxt * (HH * HSTR);

        // ---- stage 64 steps of x, transposed to [t][row] ----
        if ((t & 63) == 0) {
            __syncthreads();
            for (int idx = tid; idx < BR * 64; idx += NTHR) {
                const int rr = idx >> 6, tt2 = idx & 63;
                xs[tt2 * HSTR + rr] = x[(size_t)(r0 + rr) * TT + t + tt2];
            }
            __syncthreads();
        }
        const float* xrow = xs + (t & 63) * HSTR + rbase;

        // ---------------- cell 1 ----------------
        #pragma unroll
        for (int rq = 0; rq < 4; ++rq) {
            const float4 x4 = *(const float4*)(xrow + 4 * rq);
            const ull xp0 = pack2(x4.x, x4.y);
            const ull xp1 = pack2(x4.z, x4.w);
            const int rp = 2 * rq;
            acc[0][rp]   = fma2(wi1p[0], xp0, b1p[0]);
            acc[1][rp]   = fma2(wi1p[1], xp0, b1p[1]);
            acc[2][rp]   = fma2(wi1p[2], xp0, b1p[2]);
            acc[3][rp]   = fma2(wi1p[3], xp0, b1p[3]);
            acc[0][rp+1] = fma2(wi1p[0], xp1, b1p[0]);
            acc[1][rp+1] = fma2(wi1p[1], xp1, b1p[1]);
            acc[2][rp+1] = fma2(wi1p[2], xp1, b1p[2]);
            acc[3][rp+1] = fma2(wi1p[3], xp1, b1p[3]);
        }
        gemm_acc(acc, wt1, h1c + rbase);

        #pragma unroll
        for (int rp = 0; rp < 8; ++rp) {
            float iv0, iv1, fv0, fv1, gv0, gv1, ov0, ov1;
            unpack2(acc[0][rp], iv0, iv1);
            unpack2(acc[1][rp], fv0, fv1);
            unpack2(acc[2][rp], gv0, gv1);
            unpack2(acc[3][rp], ov0, ov1);
            {
                const float cn = sigf(fv0) * c1r[2*rp] + sigf(iv0) * tanhfast(gv0);
                c1r[2*rp] = cn;
                h1n[j * HSTR + rbase + 2*rp] = sigf(ov0) * tanhfast(cn);
            }
            {
                const float cn = sigf(fv1) * c1r[2*rp+1] + sigf(iv1) * tanhfast(gv1);
                c1r[2*rp+1] = cn;
                h1n[j * HSTR + rbase + 2*rp+1] = sigf(ov1) * tanhfast(cn);
            }
        }
        __syncthreads();

        // ---------------- cell 2 ----------------
        #pragma unroll
        for (int rp = 0; rp < 8; ++rp) {
            acc[0][rp] = b2p[0]; acc[1][rp] = b2p[1];
            acc[2][rp] = b2p[2]; acc[3][rp] = b2p[3];
        }
        gemm_acc(acc, wt2, h1n + rbase);
        gemm_acc(acc, wt3, h2c + rbase);

        #pragma unroll
        for (int rp = 0; rp < 8; ++rp) {
            float iv0, iv1, fv0, fv1, gv0, gv1, ov0, ov1;
            unpack2(acc[0][rp], iv0, iv1);
            unpack2(acc[1][rp], fv0, fv1);
            unpack2(acc[2][rp], gv0, gv1);
            unpack2(acc[3][rp], ov0, ov1);
            {
                const float cn = sigf(fv0) * c2r[2*rp] + sigf(iv0) * tanhfast(gv0);
                c2r[2*rp] = cn;
                h2n[j * HSTR + rbase + 2*rp] = sigf(ov0) * tanhfast(cn);
            }
            {
                const float cn = sigf(fv1) * c2r[2*rp+1] + sigf(iv1) * tanhfast(gv1);
                c2r[2*rp+1] = cn;
                h2n[j * HSTR + rbase + 2*rp+1] = sigf(ov1) * tanhfast(cn);
            }
        }
        __syncthreads();

        // ------- out projection: out_mask = h2 @ W1^T + b1 (one dot per thread) -------
        {
            float a0 = b1s[oo_out];
            const float* wr = W1s + oo_out;
            #pragma unroll 8
            for (int k = 0; k < HH; ++k) {
                a0 = fmaf(h2n[k * HSTR + rr_out], wr[k * NOUT], a0);
            }
            out[OUTS_BASE + ((size_t)(r0 + rr_out) * TT + t) * NOUT + oo_out] = a0;
        }
    }

    // ---------------- final: output_cyto = h2_final @ W2^T + b2 ----------------
    // TT even -> final h2 lives in buffer 0
    {
        const float* hf = h2s;
        float a0 = b2s[oo_out];
        const float* wr = W2s + oo_out;
        #pragma unroll 8
        for (int k = 0; k < HH; ++k) {
            a0 = fmaf(hf[k * HSTR + rr_out], wr[k * NOUT], a0);
        }
        out[(size_t)(r0 + rr_out) * NOUT + oo_out] = a0;
    }
}

extern "C" void kernel_launch(void* const* d_in, const int* in_sizes, int n_in,
                              void* d_out, int out_size)
{
    (void)n_in; (void)out_size;
    const int o = (n_in >= 2 && in_sizes[1] == 1) ? 2 : 1;

    const float* x    = (const float*)d_in[0];
    const float* wih1 = (const float*)d_in[o + 0];
    const float* whh1 = (const float*)d_in[o + 1];
    const float* bih1 = (const float*)d_in[o + 2];
    const float* bhh1 = (const float*)d_in[o + 3];
    const float* wih2 = (const float*)d_in[o + 4];
    const float* whh2 = (const float*)d_in[o + 5];
    const float* bih2 = (const float*)d_in[o + 6];
    const float* bhh2 = (const float*)d_in[o + 7];
    const float* W1   = (const float*)d_in[o + 8];
    const float* b1   = (const float*)d_in[o + 9];
    const float* W2   = (const float*)d_in[o + 10];
    const float* b2   = (const float*)d_in[o + 11];

    // 1) transpose weights into __device__ scratch (k-major, gates packed)
    transpose_w_kernel<<<(HH * HH + 255) / 256, 256>>>(whh1, wih2, whh2);

    // 2) main persistent recurrence kernel
    const size_t smem = (size_t)SM_TOT * sizeof(float);   // ~91 KB
    cudaFuncSetAttribute(lstm_kernel,
                         cudaFuncAttributeMaxDynamicSharedMemorySize, (int)smem);
    lstm_kernel<<<NCTA, NTHR, smem>>>(x, wih1, bih1, bhh1, bih2, bhh2,
                                      W1, b1, W2, b2, (float*)d_out);
}